// round 11
// baseline (speedup 1.0000x reference)
#include <cuda_runtime.h>

// Gaussian-tube ray readout.
// out[b, c] = sum_n exp(-2*r2_n - 0.5*max(t_n,0)) * mem[n, c]
// exp(-2*r2) < 7e-13 once r2 > 14, so only voxels within ~3.75 of each ray's
// line contribute above the 1e-3 rel-err threshold.
//
// Decomposition: per (ray, slice-along-dominant-axis) block, test a 15x15
// in-plane window centered on the line/plane intersection. For unit dir d
// with |d_a| >= 1/sqrt(3), a contributing voxel (perp <= 3.75) lies within
// in-plane offset 3.75*sqrt(3) + 0.5 < 7 of the rounded center. Each voxel
// belongs to exactly one slice -> no double counting.
//
// Loads are hoisted above the weight cutoff (guarded only by bounds) to
// maximize MLP; k = 0 outside the cutoff preserves exact truncation behavior.

#define W_CUT (-28.0f)   // exp(-28) ~ 7e-13; truncation ~3e-5 relative
#define HW 7             // window half-width -> 15x15 = 225 candidates

__global__ void zero_kernel(float* out, int n) {
    int i = blockIdx.x * blockDim.x + threadIdx.x;
    if (i < n) out[i] = 0.0f;
}

__global__ __launch_bounds__(256) void ray_tube_kernel(
    const float* __restrict__ mem,   // [128^3, 16]
    const float* __restrict__ ro,    // [32, 3]
    const float* __restrict__ rd,    // [32, 3] unit vectors
    float* __restrict__ out)         // [32, 16]
{
    const int b     = blockIdx.y;
    const int slice = blockIdx.x;
    const int tid   = threadIdx.x;

    const float ox = ro[3*b + 0], oy = ro[3*b + 1], oz = ro[3*b + 2];
    const float ddx = rd[3*b + 0], ddy = rd[3*b + 1], ddz = rd[3*b + 2];

    // dominant axis of the direction (|d_a| >= 1/sqrt(3))
    float ax = fabsf(ddx), ay = fabsf(ddy), az = fabsf(ddz);
    int a = 0; float da = ddx; float amax = ax;
    if (ay > amax) { a = 1; da = ddy; amax = ay; }
    if (az > amax) { a = 2; da = ddz; amax = az; }

    // line/plane intersection parameter and point (block-uniform)
    const float oa = (a == 0) ? ox : ((a == 1) ? oy : oz);
    const float tc = ((float)slice - oa) / da;

    // positive-t decay kill: |t - tc| <= sqrt(2)*7 < 10 within the window;
    // if tc - 10 > 56 then w <= -0.5*t < -28 even at r2 = 0. (uniform exit)
    if (tc - 10.0f > 56.0f) return;

    const float cx = fmaf(tc, ddx, ox);
    const float cy = fmaf(tc, ddy, oy);
    const float cz = fmaf(tc, ddz, oz);

    float cu, cv;
    if (a == 0)      { cu = cy; cv = cz; }
    else if (a == 1) { cu = cx; cv = cz; }
    else             { cu = cx; cv = cy; }

    const int cu0 = __float2int_rn(cu);
    const int cv0 = __float2int_rn(cv);
    // window entirely outside the grid in-plane (uniform exit)
    if (cu0 + HW < 0 || cu0 - HW > 127) return;
    if (cv0 + HW < 0 || cv0 - HW > 127) return;

    float k = 0.0f;
    float4 m0 = {0,0,0,0}, m1 = {0,0,0,0}, m2 = {0,0,0,0}, m3 = {0,0,0,0};

    if (tid < (2*HW + 1) * (2*HW + 1)) {
        const int iu = cu0 - HW + tid / (2*HW + 1);
        const int iv = cv0 - HW + tid % (2*HW + 1);
        if (iu >= 0 && iu < 128 && iv >= 0 && iv < 128) {
            int x, y, z;
            if (a == 0)      { x = slice; y = iu;    z = iv;    }
            else if (a == 1) { x = iu;    y = slice; z = iv;    }
            else             { x = iu;    y = iv;    z = slice; }

            // issue the 64B row load immediately (address needs no FP math)
            const size_t n = (size_t)((x << 14) + (y << 7) + z);
            const float4* m = (const float4*)(mem + n * 16);
            m0 = m[0]; m1 = m[1]; m2 = m[2]; m3 = m[3];

            // residual form, matching the reference's formula exactly
            const float fx = (float)x - ox;
            const float fy = (float)y - oy;
            const float fz = (float)z - oz;
            const float t  = fx*ddx + fy*ddy + fz*ddz;
            const float rx = fmaf(-t, ddx, fx);
            const float ry = fmaf(-t, ddy, fy);
            const float rz = fmaf(-t, ddz, fz);
            const float r2 = rx*rx + ry*ry + rz*rz;
            const float w  = -2.0f * r2 - 0.5f * fmaxf(t, 0.0f);

            k = (w > W_CUT) ? __expf(w) : 0.0f;
        }
    }

    float acc[16];
    acc[0]  = k * m0.x;  acc[1]  = k * m0.y;
    acc[2]  = k * m0.z;  acc[3]  = k * m0.w;
    acc[4]  = k * m1.x;  acc[5]  = k * m1.y;
    acc[6]  = k * m1.z;  acc[7]  = k * m1.w;
    acc[8]  = k * m2.x;  acc[9]  = k * m2.y;
    acc[10] = k * m2.z;  acc[11] = k * m2.w;
    acc[12] = k * m3.x;  acc[13] = k * m3.y;
    acc[14] = k * m3.z;  acc[15] = k * m3.w;

    // butterfly-reduce 16 channels across each warp
    #pragma unroll
    for (int off = 16; off > 0; off >>= 1) {
        #pragma unroll
        for (int c = 0; c < 16; c++)
            acc[c] += __shfl_xor_sync(0xFFFFFFFFu, acc[c], off);
    }

    __shared__ float sAcc[16];
    if (tid < 16) sAcc[tid] = 0.0f;
    __syncthreads();

    if ((tid & 31) == 0) {
        #pragma unroll
        for (int c = 0; c < 16; c++)
            atomicAdd(&sAcc[c], acc[c]);
    }
    __syncthreads();

    if (tid < 16) {
        const float v = sAcc[tid];
        if (v != 0.0f) atomicAdd(&out[b * 16 + tid], v);
    }
}

extern "C" void kernel_launch(void* const* d_in, const int* in_sizes, int n_in,
                              void* d_out, int out_size) {
    const float* mem = (const float*)d_in[0];
    // d_in[1] is the coordinate meshgrid -- deterministic, recomputed from
    // indices on the fly, never read.
    const float* ro  = (const float*)d_in[2];
    const float* rd  = (const float*)d_in[3];
    float* out = (float*)d_out;

    zero_kernel<<<1, 512>>>(out, out_size);   // d_out is poisoned to 0xAA

    dim3 g(128, 32);   // (slice along dominant axis, ray)
    ray_tube_kernel<<<g, 256>>>(mem, ro, rd, out);
}

// round 14
// speedup vs baseline: 1.9775x; 1.9775x over previous
#include <cuda_runtime.h>

// Gaussian-tube ray readout.
// out[b, c] = sum_n exp(-2*r2_n - 0.5*max(t_n,0)) * mem[n, c]
//
// R11 evidence: L1tex 69.6% / occ 87% -> LDG issue-count bound, not latency
// bound. So (1) loads are guarded by the weight cutoff again (only ~25
// hits/block load), and (2) the window is tightened: W_CUT=-12.5 -> R=2.5,
// half-width 5 (121 candidates, 128-thread blocks). Coverage: a contributing
// voxel (perp <= 2.5) lies within in-plane offset 2.5*sqrt(3)+0.5 = 4.83 <= 5
// of the rounded center. Truncation <= ~1e-5 relative (threshold 1e-3;
// measured slack at W_CUT=-28 was 3.3e-6).

#define W_CUT (-12.5f)   // exp(-12.5) ~ 3.7e-6
#define HW 5             // window half-width -> 11x11 = 121 candidates

__global__ void zero_kernel(float* out, int n) {
    int i = blockIdx.x * blockDim.x + threadIdx.x;
    if (i < n) out[i] = 0.0f;
}

__global__ __launch_bounds__(128) void ray_tube_kernel(
    const float* __restrict__ mem,   // [128^3, 16]
    const float* __restrict__ ro,    // [32, 3]
    const float* __restrict__ rd,    // [32, 3] unit vectors
    float* __restrict__ out)         // [32, 16]
{
    const int b     = blockIdx.y;
    const int slice = blockIdx.x;
    const int tid   = threadIdx.x;

    const float ox = ro[3*b + 0], oy = ro[3*b + 1], oz = ro[3*b + 2];
    const float ddx = rd[3*b + 0], ddy = rd[3*b + 1], ddz = rd[3*b + 2];

    // dominant axis of the direction (|d_a| >= 1/sqrt(3))
    float ax = fabsf(ddx), ay = fabsf(ddy), az = fabsf(ddz);
    int a = 0; float da = ddx; float amax = ax;
    if (ay > amax) { a = 1; da = ddy; amax = ay; }
    if (az > amax) { a = 2; da = ddz; amax = az; }

    // line/plane intersection parameter and point (block-uniform)
    const float oa = (a == 0) ? ox : ((a == 1) ? oy : oz);
    const float tc = ((float)slice - oa) / da;

    // positive-t decay kill: in-plane offset <= sqrt(2)*5 + rounding < 8;
    // if tc - 8 > 25 then w <= -0.5*t < -12.5 even at r2 = 0. (uniform exit)
    if (tc - 8.0f > 25.0f) return;

    const float cx = fmaf(tc, ddx, ox);
    const float cy = fmaf(tc, ddy, oy);
    const float cz = fmaf(tc, ddz, oz);

    float cu, cv;
    if (a == 0)      { cu = cy; cv = cz; }
    else if (a == 1) { cu = cx; cv = cz; }
    else             { cu = cx; cv = cy; }

    const int cu0 = __float2int_rn(cu);
    const int cv0 = __float2int_rn(cv);
    // window entirely outside the grid in-plane (uniform exit)
    if (cu0 + HW < 0 || cu0 - HW > 127) return;
    if (cv0 + HW < 0 || cv0 - HW > 127) return;

    float acc[16];
    #pragma unroll
    for (int c = 0; c < 16; c++) acc[c] = 0.0f;

    if (tid < (2*HW + 1) * (2*HW + 1)) {
        const int iu = cu0 - HW + tid / (2*HW + 1);
        const int iv = cv0 - HW + tid % (2*HW + 1);
        if (iu >= 0 && iu < 128 && iv >= 0 && iv < 128) {
            int x, y, z;
            if (a == 0)      { x = slice; y = iu;    z = iv;    }
            else if (a == 1) { x = iu;    y = slice; z = iv;    }
            else             { x = iu;    y = iv;    z = slice; }

            // residual form, matching the reference's formula exactly
            const float fx = (float)x - ox;
            const float fy = (float)y - oy;
            const float fz = (float)z - oz;
            const float t  = fx*ddx + fy*ddy + fz*ddz;
            const float rx = fmaf(-t, ddx, fx);
            const float ry = fmaf(-t, ddy, fy);
            const float rz = fmaf(-t, ddz, fz);
            const float r2 = rx*rx + ry*ry + rz*rz;
            const float w  = -2.0f * r2 - 0.5f * fmaxf(t, 0.0f);

            // load only on a real hit: LDG issue count is the measured
            // bottleneck (L1tex 69.6% with hoisted loads), latency is hidden
            // by 87% occupancy.
            if (w > W_CUT) {
                const float k = __expf(w);
                const size_t n = (size_t)((x << 14) + (y << 7) + z);
                const float4* m = (const float4*)(mem + n * 16);
                const float4 m0 = m[0], m1 = m[1], m2 = m[2], m3 = m[3];
                acc[0]  = k * m0.x;  acc[1]  = k * m0.y;
                acc[2]  = k * m0.z;  acc[3]  = k * m0.w;
                acc[4]  = k * m1.x;  acc[5]  = k * m1.y;
                acc[6]  = k * m1.z;  acc[7]  = k * m1.w;
                acc[8]  = k * m2.x;  acc[9]  = k * m2.y;
                acc[10] = k * m2.z;  acc[11] = k * m2.w;
                acc[12] = k * m3.x;  acc[13] = k * m3.y;
                acc[14] = k * m3.z;  acc[15] = k * m3.w;
            }
        }
    }

    // butterfly-reduce 16 channels across each warp
    #pragma unroll
    for (int off = 16; off > 0; off >>= 1) {
        #pragma unroll
        for (int c = 0; c < 16; c++)
            acc[c] += __shfl_xor_sync(0xFFFFFFFFu, acc[c], off);
    }

    __shared__ float sAcc[16];
    if (tid < 16) sAcc[tid] = 0.0f;
    __syncthreads();

    if ((tid & 31) == 0) {
        #pragma unroll
        for (int c = 0; c < 16; c++)
            atomicAdd(&sAcc[c], acc[c]);
    }
    __syncthreads();

    if (tid < 16) {
        const float v = sAcc[tid];
        if (v != 0.0f) atomicAdd(&out[b * 16 + tid], v);
    }
}

extern "C" void kernel_launch(void* const* d_in, const int* in_sizes, int n_in,
                              void* d_out, int out_size) {
    const float* mem = (const float*)d_in[0];
    // d_in[1] is the coordinate meshgrid -- deterministic, recomputed from
    // indices on the fly, never read.
    const float* ro  = (const float*)d_in[2];
    const float* rd  = (const float*)d_in[3];
    float* out = (float*)d_out;

    zero_kernel<<<1, 512>>>(out, out_size);   // d_out is poisoned to 0xAA

    dim3 g(128, 32);   // (slice along dominant axis, ray)
    ray_tube_kernel<<<g, 128>>>(mem, ro, rd, out);
}

// round 16
// speedup vs baseline: 2.9188x; 1.4760x over previous
#include <cuda_runtime.h>

// Gaussian-tube ray readout.
// out[b, c] = sum_n exp(-2*r2_n - 0.5*max(t_n,0)) * mem[n, c]
//
// R14 evidence (12.8us, L1=44%, no pipe saturated): after guarding loads,
// the per-block cost is dominated by reduction machinery (4 warps x 160
// butterfly instrs + smem + syncs). This version uses ONE warp per block
// with 4 candidates per thread: 4x less reduction work, no shared memory,
// no __syncthreads, and the whole grid fits in a single wave (28 CTAs/SM).
//
// Window: W_CUT=-12.5 (R=2.5), HW=5 -> 121 candidates (measured rel_err
// 5.4e-6 at these settings, 185x under the 1e-3 threshold).

#define W_CUT (-12.5f)   // exp(-12.5) ~ 3.7e-6
#define HW 5             // window half-width -> 11x11 = 121 candidates
#define NCAND ((2*HW + 1) * (2*HW + 1))   // 121

__global__ void zero_kernel(float* out, int n) {
    int i = blockIdx.x * blockDim.x + threadIdx.x;
    if (i < n) out[i] = 0.0f;
}

__global__ __launch_bounds__(32) void ray_tube_kernel(
    const float* __restrict__ mem,   // [128^3, 16]
    const float* __restrict__ ro,    // [32, 3]
    const float* __restrict__ rd,    // [32, 3] unit vectors
    float* __restrict__ out)         // [32, 16]
{
    const int b     = blockIdx.y;
    const int slice = blockIdx.x;
    const int lane  = threadIdx.x;   // 0..31

    const float ox = ro[3*b + 0], oy = ro[3*b + 1], oz = ro[3*b + 2];
    const float ddx = rd[3*b + 0], ddy = rd[3*b + 1], ddz = rd[3*b + 2];

    // dominant axis of the direction (|d_a| >= 1/sqrt(3))
    float ax = fabsf(ddx), ay = fabsf(ddy), az = fabsf(ddz);
    int a = 0; float da = ddx; float amax = ax;
    if (ay > amax) { a = 1; da = ddy; amax = ay; }
    if (az > amax) { a = 2; da = ddz; amax = az; }

    // line/plane intersection parameter and point (block-uniform)
    const float oa = (a == 0) ? ox : ((a == 1) ? oy : oz);
    const float tc = ((float)slice - oa) / da;

    // positive-t decay kill: in-plane offset <= sqrt(2)*5 + rounding < 8;
    // if tc - 8 > 25 then w <= -0.5*t < -12.5 even at r2 = 0. (uniform exit)
    if (tc - 8.0f > 25.0f) return;

    const float cx = fmaf(tc, ddx, ox);
    const float cy = fmaf(tc, ddy, oy);
    const float cz = fmaf(tc, ddz, oz);

    float cu, cv;
    if (a == 0)      { cu = cy; cv = cz; }
    else if (a == 1) { cu = cx; cv = cz; }
    else             { cu = cx; cv = cy; }

    const int cu0 = __float2int_rn(cu);
    const int cv0 = __float2int_rn(cv);
    // window entirely outside the grid in-plane (uniform exit)
    if (cu0 + HW < 0 || cu0 - HW > 127) return;
    if (cv0 + HW < 0 || cv0 - HW > 127) return;

    float acc[16];
    #pragma unroll
    for (int c = 0; c < 16; c++) acc[c] = 0.0f;

    // 4 candidates per lane: lane, lane+32, lane+64, lane+96 (121 total)
    #pragma unroll
    for (int j = 0; j < 4; j++) {
        const int idx = lane + j * 32;
        if (idx >= NCAND) break;

        const int iu = cu0 - HW + idx / (2*HW + 1);
        const int iv = cv0 - HW + idx % (2*HW + 1);
        if (iu < 0 || iu > 127 || iv < 0 || iv > 127) continue;

        int x, y, z;
        if (a == 0)      { x = slice; y = iu;    z = iv;    }
        else if (a == 1) { x = iu;    y = slice; z = iv;    }
        else             { x = iu;    y = iv;    z = slice; }

        // residual form, matching the reference's formula exactly
        const float fx = (float)x - ox;
        const float fy = (float)y - oy;
        const float fz = (float)z - oz;
        const float t  = fx*ddx + fy*ddy + fz*ddz;
        const float rx = fmaf(-t, ddx, fx);
        const float ry = fmaf(-t, ddy, fy);
        const float rz = fmaf(-t, ddz, fz);
        const float r2 = rx*rx + ry*ry + rz*rz;
        const float w  = -2.0f * r2 - 0.5f * fmaxf(t, 0.0f);

        // load only on a real hit (LDG issue count was the R11 bottleneck)
        if (w > W_CUT) {
            const float k = __expf(w);
            const size_t n = (size_t)((x << 14) + (y << 7) + z);
            const float4* m = (const float4*)(mem + n * 16);
            const float4 m0 = m[0], m1 = m[1], m2 = m[2], m3 = m[3];
            acc[0]  = fmaf(k, m0.x, acc[0]);   acc[1]  = fmaf(k, m0.y, acc[1]);
            acc[2]  = fmaf(k, m0.z, acc[2]);   acc[3]  = fmaf(k, m0.w, acc[3]);
            acc[4]  = fmaf(k, m1.x, acc[4]);   acc[5]  = fmaf(k, m1.y, acc[5]);
            acc[6]  = fmaf(k, m1.z, acc[6]);   acc[7]  = fmaf(k, m1.w, acc[7]);
            acc[8]  = fmaf(k, m2.x, acc[8]);   acc[9]  = fmaf(k, m2.y, acc[9]);
            acc[10] = fmaf(k, m2.z, acc[10]);  acc[11] = fmaf(k, m2.w, acc[11]);
            acc[12] = fmaf(k, m3.x, acc[12]);  acc[13] = fmaf(k, m3.y, acc[13]);
            acc[14] = fmaf(k, m3.z, acc[14]);  acc[15] = fmaf(k, m3.w, acc[15]);
        }
    }

    // butterfly-reduce 16 channels across the single warp; after this every
    // lane holds the full block sum for every channel
    #pragma unroll
    for (int off = 16; off > 0; off >>= 1) {
        #pragma unroll
        for (int c = 0; c < 16; c++)
            acc[c] += __shfl_xor_sync(0xFFFFFFFFu, acc[c], off);
    }

    // lane c accumulates channel c directly to global (no smem, no syncs);
    // hit-free blocks issue no atomics at all
    if (lane < 16) {
        const float v = acc[lane];
        if (v != 0.0f) atomicAdd(&out[b * 16 + lane], v);
    }
}

extern "C" void kernel_launch(void* const* d_in, const int* in_sizes, int n_in,
                              void* d_out, int out_size) {
    const float* mem = (const float*)d_in[0];
    // d_in[1] is the coordinate meshgrid -- deterministic, recomputed from
    // indices on the fly, never read.
    const float* ro  = (const float*)d_in[2];
    const float* rd  = (const float*)d_in[3];
    float* out = (float*)d_out;

    zero_kernel<<<1, 512>>>(out, out_size);   // d_out is poisoned to 0xAA

    dim3 g(128, 32);   // (slice along dominant axis, ray)
    ray_tube_kernel<<<g, 32>>>(mem, ro, rd, out);
}